// round 1
// baseline (speedup 1.0000x reference)
#include <cuda_runtime.h>
#include <cstdint>

// Problem constants (fixed by the dataset)
#define NBS   256      // graphs
#define NNOD  128      // nodes per graph
#define NDIM  64       // feature dim
#define NC    64       // codebook atoms
#define NK    32       // support points per atom
#define CKTOT (NC*NK)  // 2048

// gamma = 1/64 ; work in log2 domain:
// exp(-g*(xn+an-2*dot)) = exp2( C2*dot - A2*xn - A2*an )
#define A2f 0.0225421101f   // log2(e)/64
#define C2f 0.0450842203f   // 2*log2(e)/64

static __device__ float g_anL[CKTOT];  // A2 * ||atom_ck||^2
static __device__ float g_kyy[NC];     // within-atom kernel means

// ---------------------------------------------------------------------------
// Fast exp2 on the FMA/ALU pipes (avoids MUFU which would bottleneck at 71M exps)
// x in [-100, 0]; magic-constant round + deg-5 poly + exponent bit splice.
// ---------------------------------------------------------------------------
__device__ __forceinline__ float fexp2(float x)
{
    x = fmaxf(x, -100.0f);
    float r = x + 12582912.0f;            // 1.5*2^23 : bits(r) = 0x4B400000 + round(x)
    int   m = __float_as_int(r);          // (m<<23) == round(x)<<23  (mod 2^32)
    float t = x - (r - 12582912.0f);      // frac in [-0.5, 0.5], exact
    float p =            1.3333558e-3f;
    p = fmaf(p, t, 9.6181291e-3f);
    p = fmaf(p, t, 5.5504109e-2f);
    p = fmaf(p, t, 2.4022651e-1f);
    p = fmaf(p, t, 6.9314718e-1f);
    p = fmaf(p, t, 1.0f);
    return __int_as_float(__float_as_int(p) + (m << 23));
}

__device__ __forceinline__ float wred(float v)
{
#pragma unroll
    for (int o = 16; o; o >>= 1) v += __shfl_xor_sync(0xffffffffu, v, o);
    return v;
}

// XOR-swizzled smem tile: row-major [row][64], float4 slot f4' = f4 ^ (row&15).
// Keeps 16B alignment, conflict-free fragment reads, no padding.
__device__ __forceinline__ int tile_off(int row, int k4)
{
    return (row << 6) + ((k4 ^ (row & 15)) << 2);
}

// 128x128x64 register-tiled GEMM piece: thread (ty,tx) computes rows ty*8..+7
// against interleaved columns {tx, tx+16, ..., tx+112}. acc[i][m].
__device__ __forceinline__ void gemm_tile(const float* __restrict__ A,
                                          const float* __restrict__ B,
                                          int ty, int tx, float acc[8][8])
{
#pragma unroll
    for (int i = 0; i < 8; ++i)
#pragma unroll
        for (int m = 0; m < 8; ++m) acc[i][m] = 0.0f;

#pragma unroll 1
    for (int kk = 0; kk < NDIM; kk += 2) {
        const int k4 = kk >> 2, rr = kk & 3;
        float2 a2[8];
#pragma unroll
        for (int i = 0; i < 8; ++i)
            a2[i] = *(const float2*)(A + tile_off(ty * 8 + i, k4) + rr);
#pragma unroll
        for (int m = 0; m < 8; ++m) {
            float2 b2 = *(const float2*)(B + tile_off(m * 16 + tx, k4) + rr);
#pragma unroll
            for (int i = 0; i < 8; ++i) {
                acc[i][m] = fmaf(a2[i].x, b2.x, acc[i][m]);
                acc[i][m] = fmaf(a2[i].y, b2.y, acc[i][m]);
            }
        }
    }
}

// ---------------------------------------------------------------------------
// Prep: per-atom scaled norms + k_yy. 64 blocks x 128 threads, trivial cost.
// ---------------------------------------------------------------------------
__global__ void mmd_prep(const float* __restrict__ atoms)
{
    __shared__ float at[NK][NDIM + 4];
    __shared__ float anl[NK];
    __shared__ float ssum;
    const int c = blockIdx.x, tid = threadIdx.x;

    const float4* ag = (const float4*)(atoms + (size_t)c * NK * NDIM);
#pragma unroll
    for (int t = 0; t < 4; ++t) {
        int idx = t * 128 + tid;          // 0..511 float4s
        int row = idx >> 4, k4 = idx & 15;
        *(float4*)&at[row][k4 * 4] = ag[idx];
    }
    if (tid == 0) ssum = 0.0f;
    __syncthreads();

    if (tid < NK) {
        float s = 0.0f;
#pragma unroll
        for (int k = 0; k < NDIM; k += 4) {
            float4 v = *(const float4*)&at[tid][k];
            s = fmaf(v.x, v.x, fmaf(v.y, v.y, fmaf(v.z, v.z, fmaf(v.w, v.w, s))));
        }
        anl[tid] = s;
        g_anL[c * NK + tid] = s * A2f;
    }
    __syncthreads();

    float ps = 0.0f;
#pragma unroll
    for (int t = 0; t < 8; ++t) {
        int p = t * 128 + tid;            // 1024 pairs
        int i = p >> 5, j = p & 31;
        float dot = 0.0f;
#pragma unroll
        for (int k = 0; k < NDIM; k += 4) {
            float4 a  = *(const float4*)&at[i][k];
            float4 bb = *(const float4*)&at[j][k];
            dot = fmaf(a.x, bb.x, fmaf(a.y, bb.y, fmaf(a.z, bb.z, fmaf(a.w, bb.w, dot))));
        }
        ps += fexp2(fmaf(dot, C2f, -A2f * (anl[i] + anl[j])));
    }
    ps = wred(ps);
    if ((tid & 31) == 0) atomicAdd(&ssum, ps);
    __syncthreads();
    if (tid == 0) g_kyy[c] = ssum * (1.0f / (NK * NK));
}

// ---------------------------------------------------------------------------
// Main: one block per graph. Fused k_xx + k_xy with exp2 epilogue & reduction.
// ---------------------------------------------------------------------------
#define SMEM_FLOATS (8192 + 8192 + 128 + 128 + 64 + 32)
#define SMEM_BYTES  (SMEM_FLOATS * 4)

__global__ void __launch_bounds__(256, 2)
mmd_main(const float* __restrict__ x, const float* __restrict__ atoms,
         float* __restrict__ out)
{
    extern __shared__ float smem[];
    float* xs   = smem;            // 128x64 swizzled x tile
    float* ats  = smem + 8192;     // 128x64 swizzled atom chunk
    float* xnL  = smem + 16384;    // A2*||x_n||^2
    float* anLs = smem + 16512;    // chunk slice of g_anL
    float* red  = smem + 16640;    // [64] k_xy sums per atom
    float* kxxp = smem + 16704;    // [0] = k_xx sum

    const int tid  = threadIdx.x;
    const int b    = blockIdx.x;
    const int tx   = tid & 15, ty = tid >> 4;
    const int lane = tid & 31;

    if (tid < NC) red[tid] = 0.0f;
    if (tid == 0) kxxp[0] = 0.0f;

    // load x tile (coalesced float4) into swizzled smem
    const float4* xg = (const float4*)(x + (size_t)b * NNOD * NDIM);
#pragma unroll
    for (int it = 0; it < 8; ++it) {
        int idx = it * 256 + tid;          // 0..2047 float4s
        int row = idx >> 4, k4 = idx & 15;
        *(float4*)(xs + tile_off(row, k4)) = xg[idx];
    }
    __syncthreads();

    if (tid < NNOD) {
        float s = 0.0f;
#pragma unroll
        for (int k4 = 0; k4 < 16; ++k4) {
            float4 v = *(const float4*)(xs + tile_off(tid, k4));
            s = fmaf(v.x, v.x, fmaf(v.y, v.y, fmaf(v.z, v.z, fmaf(v.w, v.w, s))));
        }
        xnL[tid] = s * A2f;
    }
    __syncthreads();

    // ---------------- k_xx ----------------
    {
        float acc[8][8];
        gemm_tile(xs, xs, ty, tx, acc);
        float xv[8], bv[8];
#pragma unroll
        for (int i = 0; i < 8; ++i) xv[i] = xnL[ty * 8 + i];
#pragma unroll
        for (int m = 0; m < 8; ++m) bv[m] = xnL[m * 16 + tx];
        float ps = 0.0f;
#pragma unroll
        for (int m = 0; m < 8; ++m)
#pragma unroll
            for (int i = 0; i < 8; ++i)
                ps += fexp2(fmaf(acc[i][m], C2f, -xv[i]) - bv[m]);
        ps = wred(ps);
        if (lane == 0) atomicAdd(kxxp, ps);
    }

    // ---------------- k_xy over 16 atom chunks (4 atoms each) ----------------
#pragma unroll 1
    for (int ch = 0; ch < 16; ++ch) {
        __syncthreads();   // protect ats reuse
        const float4* ag = (const float4*)(atoms + (size_t)ch * 128 * NDIM);
#pragma unroll
        for (int it = 0; it < 8; ++it) {
            int idx = it * 256 + tid;
            int row = idx >> 4, k4 = idx & 15;
            *(float4*)(ats + tile_off(row, k4)) = ag[idx];
        }
        if (tid < 128) anLs[tid] = g_anL[ch * 128 + tid];
        __syncthreads();

        float acc[8][8];
        gemm_tile(xs, ats, ty, tx, acc);

        float xv[8], av[8];
#pragma unroll
        for (int i = 0; i < 8; ++i) xv[i] = xnL[ty * 8 + i];
#pragma unroll
        for (int m = 0; m < 8; ++m) av[m] = anLs[m * 16 + tx];

        // column j = m*16+tx -> atom-in-chunk = (m*16+tx)>>5 = m>>1
        float ps[4] = {0.0f, 0.0f, 0.0f, 0.0f};
#pragma unroll
        for (int m = 0; m < 8; ++m) {
            float bvm = av[m];
            float acu = 0.0f;
#pragma unroll
            for (int i = 0; i < 8; ++i)
                acu += fexp2(fmaf(acc[i][m], C2f, -xv[i]) - bvm);
            ps[m >> 1] += acu;
        }
#pragma unroll
        for (int q = 0; q < 4; ++q) {
            float v = wred(ps[q]);
            if (lane == 0) atomicAdd(&red[ch * 4 + q], v);
        }
    }
    __syncthreads();

    if (tid < NC) {
        float kxy = red[tid]  * (1.0f / (NNOD * NK));
        float kxx = kxxp[0]   * (1.0f / (NNOD * NNOD));
        out[b * NC + tid] = kxx + g_kyy[tid] - 2.0f * kxy;
    }
}

// ---------------------------------------------------------------------------
extern "C" void kernel_launch(void* const* d_in, const int* in_sizes, int n_in,
                              void* d_out, int out_size)
{
    const float* x     = (const float*)d_in[0];
    const float* atoms = (const float*)d_in[1];
    // defensive: identify by element counts in case of metadata reordering
    if (n_in >= 2 && in_sizes[0] == CKTOT * NDIM && in_sizes[1] == NBS * NNOD * NDIM) {
        x     = (const float*)d_in[1];
        atoms = (const float*)d_in[0];
    }
    float* out = (float*)d_out;

    cudaFuncSetAttribute(mmd_main, cudaFuncAttributeMaxDynamicSharedMemorySize,
                         SMEM_BYTES);

    mmd_prep<<<NC, 128>>>(atoms);
    mmd_main<<<NBS, 256, SMEM_BYTES>>>(x, atoms, out);
}

// round 3
// speedup vs baseline: 2.2921x; 2.2921x over previous
#include <cuda_runtime.h>
#include <cuda_bf16.h>
#include <cstdint>

#define NBS   256
#define NNOD  128
#define NDIM  64
#define NC    64
#define NK    32
#define CKTOT (NC*NK)

#define A2f 0.0225421101f     // log2(e)/64
#define C2f 0.0450842203f     // 2*log2(e)/64
#define S1f 0.21233045f       // sqrt(C2f): scale inputs so MMA acc = C2*dot

// ---------------- smem layout (byte offsets from 1KB-aligned base) ----------
#define OFF_XHI   0           // 128x64 bf16 SW128 (16KB)
#define OFF_XLO   16384
#define OFF_AT(b) (32768 + (b)*32768)    // atom chunk buf: hi, lo at +16384
#define OFF_XNL   98304       // float[128]
#define OFF_RED   98816       // float[65]
#define SMEM_DYN  (99328 + 1024)

// pre-converted atoms: scaled bf16 hi/lo, already in SW128 tile byte order
static __device__ uint16_t g_at_hi[CKTOT * NDIM];
static __device__ uint16_t g_at_lo[CKTOT * NDIM];
static __device__ float    g_anL[CKTOT];   // A2*||atom_ck||^2
static __device__ float    g_kyy[NC];

// ---------------------------------------------------------------------------
__device__ __forceinline__ uint32_t smem_u32(const void* p) {
    uint32_t a;
    asm("{ .reg .u64 t; cvta.to.shared.u64 t, %1; cvt.u32.u64 %0, t; }" : "=r"(a) : "l"(p));
    return a;
}
__device__ __forceinline__ uint32_t sw128(uint32_t o) { return o ^ ((o >> 3) & 0x70); }

__device__ __forceinline__ void ldsm4(uint32_t r[4], uint32_t addr) {
    asm volatile("ldmatrix.sync.aligned.m8n8.x4.shared.b16 {%0,%1,%2,%3}, [%4];"
                 : "=r"(r[0]), "=r"(r[1]), "=r"(r[2]), "=r"(r[3]) : "r"(addr));
}
__device__ __forceinline__ void mma16816(float c[4], const uint32_t a[4], const uint32_t b[2]) {
    asm volatile("mma.sync.aligned.m16n8k16.row.col.f32.bf16.bf16.f32 "
                 "{%0,%1,%2,%3}, {%4,%5,%6,%7}, {%8,%9}, {%0,%1,%2,%3};"
                 : "+f"(c[0]), "+f"(c[1]), "+f"(c[2]), "+f"(c[3])
                 : "r"(a[0]), "r"(a[1]), "r"(a[2]), "r"(a[3]), "r"(b[0]), "r"(b[1]));
}
__device__ __forceinline__ void cp16(uint32_t dst, const void* src) {
    asm volatile("cp.async.cg.shared.global [%0], [%1], 16;" :: "r"(dst), "l"(src) : "memory");
}
#define CP_COMMIT() asm volatile("cp.async.commit_group;" ::: "memory")
#define CP_WAIT0()  asm volatile("cp.async.wait_group 0;" ::: "memory")

// exp2 on the FMA pipe (args here are in [-~15, ~0])
__device__ __forceinline__ float fexp2(float x) {
    float r = x + 12582912.0f;
    int   m = __float_as_int(r);
    float t = x - (r - 12582912.0f);
    float p =            1.3333558e-3f;
    p = fmaf(p, t, 9.6181291e-3f);
    p = fmaf(p, t, 5.5504109e-2f);
    p = fmaf(p, t, 2.4022651e-1f);
    p = fmaf(p, t, 6.9314718e-1f);
    p = fmaf(p, t, 1.0f);
    return __int_as_float(__float_as_int(p) + (m << 23));
}
__device__ __forceinline__ float wred(float v) {
#pragma unroll
    for (int o = 16; o; o >>= 1) v += __shfl_xor_sync(0xffffffffu, v, o);
    return v;
}

// ---------------------------------------------------------------------------
// Prep: per-ck-row scaled norms, k_yy, bf16 hi/lo atoms in pre-swizzled layout
// ---------------------------------------------------------------------------
__global__ void mmd_prep(const float* __restrict__ atoms)
{
    __shared__ float at[NK][NDIM + 4];
    __shared__ float anl[NK];
    __shared__ float ssum;
    const int c = blockIdx.x, tid = threadIdx.x;

    const float4* ag = (const float4*)(atoms + (size_t)c * NK * NDIM);
#pragma unroll
    for (int t = 0; t < 4; ++t) {
        int idx = t * 128 + tid;
        int row = idx >> 4, k4 = idx & 15;
        *(float4*)&at[row][k4 * 4] = ag[idx];
    }
    if (tid == 0) ssum = 0.0f;
    __syncthreads();

    if (tid < NK) {
        float s = 0.0f;
#pragma unroll
        for (int k = 0; k < NDIM; k += 4) {
            float4 v = *(const float4*)&at[tid][k];
            s = fmaf(v.x, v.x, fmaf(v.y, v.y, fmaf(v.z, v.z, fmaf(v.w, v.w, s))));
        }
        anl[tid] = s;
        g_anL[c * NK + tid] = s * A2f;
    }
    __syncthreads();

#pragma unroll
    for (int t = 0; t < 16; ++t) {
        int idx = t * 128 + tid;            // 0..2047
        int r = idx >> 6, k = idx & 63;
        float v = at[r][k] * S1f;
        __nv_bfloat16 hi = __float2bfloat16(v);
        __nv_bfloat16 lo = __float2bfloat16(v - __bfloat162float(hi));
        int gr = c * NK + r;
        int chunk = gr >> 7, rin = gr & 127;
        uint32_t off = sw128((uint32_t)(rin * 128 + k * 2));
        uint32_t i16 = (uint32_t)chunk * 8192u + (off >> 1);
        g_at_hi[i16] = __bfloat16_as_ushort(hi);
        g_at_lo[i16] = __bfloat16_as_ushort(lo);
    }

    float ps = 0.0f;
#pragma unroll
    for (int t = 0; t < 8; ++t) {
        int p = t * 128 + tid;
        int i = p >> 5, j = p & 31;
        float dot = 0.0f;
#pragma unroll
        for (int k = 0; k < NDIM; k += 4) {
            float4 a  = *(const float4*)&at[i][k];
            float4 bb = *(const float4*)&at[j][k];
            dot = fmaf(a.x, bb.x, fmaf(a.y, bb.y, fmaf(a.z, bb.z, fmaf(a.w, bb.w, dot))));
        }
        ps += fexp2(fmaf(dot, C2f, -A2f * (anl[i] + anl[j])));
    }
    ps = wred(ps);
    if ((tid & 31) == 0) atomicAdd(&ssum, ps);
    __syncthreads();
    if (tid == 0) g_kyy[c] = ssum * (1.0f / (NK * NK));
}

// ---------------------------------------------------------------------------
// Main: one CTA per graph; mma.sync bf16 3-pass + fused exp2 epilogue
// ---------------------------------------------------------------------------
__global__ void __launch_bounds__(256, 2)
mmd_main(const float* __restrict__ x, float* __restrict__ out)
{
    extern __shared__ char sraw[];
    char* sm = (char*)(((uintptr_t)sraw + 1023) & ~(uintptr_t)1023);
    const uint32_t sb = smem_u32(sm);

    float* xnL = (float*)(sm + OFF_XNL);
    float* red = (float*)(sm + OFF_RED);

    const int tid = threadIdx.x, wid = tid >> 5, l = tid & 31;
    const int b  = blockIdx.x;
    const int wm = wid >> 2;      // row half   (0..1)  -> rows wm*64..+63
    const int wn = wid & 3;       // col quarter(0..3)  -> cols wn*32..+31 = one atom

    if (tid < 65) red[tid] = 0.0f;

    // ---- prefetch atom chunk 0 into buf 0 (overlaps x conversion) ----
    {
        const uint4* gh = (const uint4*)g_at_hi;
        const uint4* gl = (const uint4*)g_at_lo;
        uint32_t dh = sb + OFF_AT(0), dl = dh + 16384;
#pragma unroll
        for (int t = 0; t < 4; ++t) {
            int i = t * 256 + tid;
            cp16(dh + i * 16, gh + i);
            cp16(dl + i * 16, gl + i);
        }
        CP_COMMIT();
    }

    // ---- x tile: scaled bf16 hi/lo into SW128 smem ----
    const float4* xg = (const float4*)(x + (size_t)b * NNOD * NDIM);
#pragma unroll
    for (int t = 0; t < 8; ++t) {
        int idx = t * 256 + tid;               // 0..2047 float4
        int row = idx >> 4, k4 = idx & 15;
        float4 v = xg[idx];
        float s0 = v.x * S1f, s1 = v.y * S1f, s2 = v.z * S1f, s3 = v.w * S1f;
        __nv_bfloat16 h0 = __float2bfloat16(s0), h1 = __float2bfloat16(s1);
        __nv_bfloat16 h2 = __float2bfloat16(s2), h3 = __float2bfloat16(s3);
        __nv_bfloat16 l0 = __float2bfloat16(s0 - __bfloat162float(h0));
        __nv_bfloat16 l1 = __float2bfloat16(s1 - __bfloat162float(h1));
        __nv_bfloat16 l2 = __float2bfloat16(s2 - __bfloat162float(h2));
        __nv_bfloat16 l3 = __float2bfloat16(s3 - __bfloat162float(h3));
        uint32_t off = sw128((uint32_t)(row * 128 + k4 * 8));
        uint2 ph, pl;
        ph.x = (uint32_t)__bfloat16_as_ushort(h0) | ((uint32_t)__bfloat16_as_ushort(h1) << 16);
        ph.y = (uint32_t)__bfloat16_as_ushort(h2) | ((uint32_t)__bfloat16_as_ushort(h3) << 16);
        pl.x = (uint32_t)__bfloat16_as_ushort(l0) | ((uint32_t)__bfloat16_as_ushort(l1) << 16);
        pl.y = (uint32_t)__bfloat16_as_ushort(l2) | ((uint32_t)__bfloat16_as_ushort(l3) << 16);
        *(uint2*)(sm + OFF_XHI + off) = ph;
        *(uint2*)(sm + OFF_XLO + off) = pl;
    }
    if (tid < NNOD) {
        const float4* xr4 = (const float4*)(x + ((size_t)b * NNOD + tid) * NDIM);
        float s = 0.0f;
#pragma unroll
        for (int k = 0; k < 16; ++k) {
            float4 v = xr4[k];
            s = fmaf(v.x, v.x, fmaf(v.y, v.y, fmaf(v.z, v.z, fmaf(v.w, v.w, s))));
        }
        xnL[tid] = s * A2f;
    }
    CP_WAIT0();
    __syncthreads();

    // ---- per-thread ldmatrix address components ----
    const uint32_t mask  = (uint32_t)((l & 7) << 4);
    const uint32_t aRow  = (uint32_t)((wm * 64 + (l & 7) + ((l >> 3) & 1) * 8) * 128);
    const uint32_t klowA = (uint32_t)(((l >> 4) & 1) * 16);
    const uint32_t bRow  = (uint32_t)((wn * 32 + (l & 7) + ((l >> 4) & 1) * 8) * 128);
    const uint32_t klowB = (uint32_t)(((l >> 3) & 1) * 16);

    // hoisted row norms for the epilogue: rows wm*64 + mt*16 + (l>>2) + r*8
    float xr[8];
#pragma unroll
    for (int mt = 0; mt < 4; ++mt) {
        xr[mt * 2 + 0] = xnL[wm * 64 + mt * 16 + (l >> 2)];
        xr[mt * 2 + 1] = xnL[wm * 64 + mt * 16 + (l >> 2) + 8];
    }

    // ---- 17 chunks: 16 atom chunks + k_xx (B = x tile) ----
#pragma unroll 1
    for (int ch = 0; ch < 17; ++ch) {
        const int buf = ch & 1;

        if (ch + 1 < 16) {   // prefetch next atom chunk into buf^1
            const uint4* gh = (const uint4*)g_at_hi + (size_t)(ch + 1) * 1024;
            const uint4* gl = (const uint4*)g_at_lo + (size_t)(ch + 1) * 1024;
            uint32_t dh = sb + OFF_AT(buf ^ 1), dl = dh + 16384;
#pragma unroll
            for (int t = 0; t < 4; ++t) {
                int i = t * 256 + tid;
                cp16(dh + i * 16, gh + i);
                cp16(dl + i * 16, gl + i);
            }
        }
        CP_COMMIT();

        const uint32_t Ahi = sb + OFF_XHI, Alo = sb + OFF_XLO;
        const uint32_t Bhi = (ch == 16) ? Ahi : (sb + OFF_AT(buf));
        const uint32_t Blo = (ch == 16) ? Alo : (sb + OFF_AT(buf) + 16384);

        float c[4][4][4];
#pragma unroll
        for (int mt = 0; mt < 4; ++mt)
#pragma unroll
            for (int nt = 0; nt < 4; ++nt)
#pragma unroll
                for (int q = 0; q < 4; ++q) c[mt][nt][q] = 0.0f;

#pragma unroll
        for (int pass = 0; pass < 3; ++pass) {
            const uint32_t Ab = (pass == 2) ? Alo : Ahi;
            const uint32_t Bb = (pass == 1) ? Blo : Bhi;
#pragma unroll
            for (int ks = 0; ks < 4; ++ks) {
                uint32_t a[4][4];
#pragma unroll
                for (int mt = 0; mt < 4; ++mt)
                    ldsm4(a[mt], Ab + aRow + mt * 2048 + (((uint32_t)(ks * 32) + klowA) ^ mask));
#pragma unroll
                for (int np = 0; np < 2; ++np) {
                    uint32_t bb[4];
                    ldsm4(bb, Bb + bRow + np * 2048 + (((uint32_t)(ks * 32) + klowB) ^ mask));
#pragma unroll
                    for (int mt = 0; mt < 4; ++mt) {
                        mma16816(c[mt][np * 2 + 0], a[mt], bb + 0);
                        mma16816(c[mt][np * 2 + 1], a[mt], bb + 2);
                    }
                }
            }
        }

        // ---- epilogue: exp2 + per-atom reduction ----
        float cn[8];
        if (ch == 16) {
#pragma unroll
            for (int nt = 0; nt < 4; ++nt) {
                cn[nt * 2 + 0] = xnL[wn * 32 + nt * 8 + (l & 3) * 2];
                cn[nt * 2 + 1] = xnL[wn * 32 + nt * 8 + (l & 3) * 2 + 1];
            }
        } else {
#pragma unroll
            for (int nt = 0; nt < 4; ++nt) {
                cn[nt * 2 + 0] = __ldg(&g_anL[ch * 128 + wn * 32 + nt * 8 + (l & 3) * 2]);
                cn[nt * 2 + 1] = __ldg(&g_anL[ch * 128 + wn * 32 + nt * 8 + (l & 3) * 2 + 1]);
            }
        }
        float s0 = 0.f, s1 = 0.f;
#pragma unroll
        for (int mt = 0; mt < 4; ++mt)
#pragma unroll
            for (int nt = 0; nt < 4; ++nt) {
                s0 += fexp2(c[mt][nt][0] - xr[mt * 2 + 0] - cn[nt * 2 + 0]);
                s1 += fexp2(c[mt][nt][1] - xr[mt * 2 + 0] - cn[nt * 2 + 1]);
                s0 += fexp2(c[mt][nt][2] - xr[mt * 2 + 1] - cn[nt * 2 + 0]);
                s1 += fexp2(c[mt][nt][3] - xr[mt * 2 + 1] - cn[nt * 2 + 1]);
            }
        float s = wred(s0 + s1);
        if (l == 0) atomicAdd(&red[(ch == 16) ? 64 : (ch * 4 + wn)], s);

        CP_WAIT0();
        __syncthreads();
    }

    if (tid < NC) {
        float kxy = red[tid] * (1.0f / (NNOD * NK));
        float kxx = red[64]  * (1.0f / (NNOD * NNOD));
        out[b * NC + tid] = kxx + g_kyy[tid] - 2.0f * kxy;
    }
}

// ---------------------------------------------------------------------------
extern "C" void kernel_launch(void* const* d_in, const int* in_sizes, int n_in,
                              void* d_out, int out_size)
{
    const float* x     = (const float*)d_in[0];
    const float* atoms = (const float*)d_in[1];
    if (n_in >= 2 && in_sizes[0] == CKTOT * NDIM && in_sizes[1] == NBS * NNOD * NDIM) {
        x     = (const float*)d_in[1];
        atoms = (const float*)d_in[0];
    }
    float* out = (float*)d_out;

    cudaFuncSetAttribute(mmd_main, cudaFuncAttributeMaxDynamicSharedMemorySize, SMEM_DYN);

    mmd_prep<<<NC, 128>>>(atoms);
    mmd_main<<<NBS, 256, SMEM_DYN>>>(x, out);
}

// round 4
// speedup vs baseline: 3.7031x; 1.6156x over previous
#include <cuda_runtime.h>
#include <cuda_fp16.h>
#include <cstdint>

#define NBS   256
#define NNOD  128
#define NDIM  64
#define NC    64
#define NK    32
#define CKTOT (NC*NK)

#define A2f 0.0225421101f     // log2(e)/64
#define C2f 0.0450842203f     // 2*log2(e)/64
#define S1f 0.21233045f       // sqrt(C2f): scale inputs so MMA acc = C2*dot

// ---------------- smem layout (byte offsets from 1KB-aligned base) ----------
#define OFF_XHI   0           // 128x64 fp16 SW128 (16KB)
#define OFF_XLO   16384
#define OFF_AT(b) (32768 + (b)*16384)    // atom chunk bufs (fp16, 16KB each)
#define OFF_XNL   65536       // float[128]
#define OFF_RED   66048       // float[65]
#define SMEM_DYN  (66560 + 1024)

// pre-converted atoms: scaled fp16, already in SW128 tile byte order
static __device__ uint16_t g_at_h[CKTOT * NDIM];
static __device__ float    g_anL[CKTOT];   // A2*||atom_ck||^2
static __device__ float    g_kyy[NC];

// ---------------------------------------------------------------------------
__device__ __forceinline__ uint32_t smem_u32(const void* p) {
    uint32_t a;
    asm("{ .reg .u64 t; cvta.to.shared.u64 t, %1; cvt.u32.u64 %0, t; }" : "=r"(a) : "l"(p));
    return a;
}
__device__ __forceinline__ uint32_t sw128(uint32_t o) { return o ^ ((o >> 3) & 0x70); }

__device__ __forceinline__ void ldsm4(uint32_t r[4], uint32_t addr) {
    asm volatile("ldmatrix.sync.aligned.m8n8.x4.shared.b16 {%0,%1,%2,%3}, [%4];"
                 : "=r"(r[0]), "=r"(r[1]), "=r"(r[2]), "=r"(r[3]) : "r"(addr));
}
__device__ __forceinline__ void mma16816(float c[4], const uint32_t a[4], const uint32_t b[2]) {
    asm volatile("mma.sync.aligned.m16n8k16.row.col.f32.f16.f16.f32 "
                 "{%0,%1,%2,%3}, {%4,%5,%6,%7}, {%8,%9}, {%0,%1,%2,%3};"
                 : "+f"(c[0]), "+f"(c[1]), "+f"(c[2]), "+f"(c[3])
                 : "r"(a[0]), "r"(a[1]), "r"(a[2]), "r"(a[3]), "r"(b[0]), "r"(b[1]));
}
__device__ __forceinline__ void cp16(uint32_t dst, const void* src) {
    asm volatile("cp.async.cg.shared.global [%0], [%1], 16;" :: "r"(dst), "l"(src) : "memory");
}
#define CP_COMMIT() asm volatile("cp.async.commit_group;" ::: "memory")
#define CP_WAIT0()  asm volatile("cp.async.wait_group 0;" ::: "memory")

// exp2 on the FMA pipe (args in [-~15, 0])
__device__ __forceinline__ float fexp2(float x) {
    float r = x + 12582912.0f;
    int   m = __float_as_int(r);
    float t = x - (r - 12582912.0f);
    float p =            1.3333558e-3f;
    p = fmaf(p, t, 9.6181291e-3f);
    p = fmaf(p, t, 5.5504109e-2f);
    p = fmaf(p, t, 2.4022651e-1f);
    p = fmaf(p, t, 6.9314718e-1f);
    p = fmaf(p, t, 1.0f);
    return __int_as_float(__float_as_int(p) + (m << 23));
}
__device__ __forceinline__ float wred(float v) {
#pragma unroll
    for (int o = 16; o; o >>= 1) v += __shfl_xor_sync(0xffffffffu, v, o);
    return v;
}

// ---------------------------------------------------------------------------
// Prep: per-ck-row scaled norms, k_yy, fp16 atoms in pre-swizzled layout
// ---------------------------------------------------------------------------
__global__ void mmd_prep(const float* __restrict__ atoms)
{
    __shared__ float at[NK][NDIM + 4];
    __shared__ float anl[NK];
    __shared__ float ssum;
    const int c = blockIdx.x, tid = threadIdx.x;

    const float4* ag = (const float4*)(atoms + (size_t)c * NK * NDIM);
#pragma unroll
    for (int t = 0; t < 4; ++t) {
        int idx = t * 128 + tid;
        int row = idx >> 4, k4 = idx & 15;
        *(float4*)&at[row][k4 * 4] = ag[idx];
    }
    if (tid == 0) ssum = 0.0f;
    __syncthreads();

    if (tid < NK) {
        float s = 0.0f;
#pragma unroll
        for (int k = 0; k < NDIM; k += 4) {
            float4 v = *(const float4*)&at[tid][k];
            s = fmaf(v.x, v.x, fmaf(v.y, v.y, fmaf(v.z, v.z, fmaf(v.w, v.w, s))));
        }
        anl[tid] = s;
        g_anL[c * NK + tid] = s * A2f;
    }
    __syncthreads();

#pragma unroll
    for (int t = 0; t < 16; ++t) {
        int idx = t * 128 + tid;            // 0..2047
        int r = idx >> 6, k = idx & 63;
        float v = at[r][k] * S1f;
        int gr = c * NK + r;
        int chunk = gr >> 7, rin = gr & 127;
        uint32_t off = sw128((uint32_t)(rin * 128 + k * 2));
        g_at_h[(uint32_t)chunk * 8192u + (off >> 1)] =
            __half_as_ushort(__float2half_rn(v));
    }

    float ps = 0.0f;
#pragma unroll
    for (int t = 0; t < 8; ++t) {
        int p = t * 128 + tid;
        int i = p >> 5, j = p & 31;
        float dot = 0.0f;
#pragma unroll
        for (int k = 0; k < NDIM; k += 4) {
            float4 a  = *(const float4*)&at[i][k];
            float4 bb = *(const float4*)&at[j][k];
            dot = fmaf(a.x, bb.x, fmaf(a.y, bb.y, fmaf(a.z, bb.z, fmaf(a.w, bb.w, dot))));
        }
        ps += fexp2(fmaf(dot, C2f, -A2f * (anl[i] + anl[j])));
    }
    ps = wred(ps);
    if ((tid & 31) == 0) atomicAdd(&ssum, ps);
    __syncthreads();
    if (tid == 0) g_kyy[c] = ssum * (1.0f / (NK * NK));
}

// ---------------------------------------------------------------------------
// Main: one CTA per graph; fp16 mma (A split hi/lo, B plain) + exp2 epilogue
// ---------------------------------------------------------------------------
__global__ void __launch_bounds__(256, 2)
mmd_main(const float* __restrict__ x, float* __restrict__ out)
{
    extern __shared__ char sraw[];
    char* sm = (char*)(((uintptr_t)sraw + 1023) & ~(uintptr_t)1023);
    const uint32_t sb = smem_u32(sm);

    float* xnL = (float*)(sm + OFF_XNL);
    float* red = (float*)(sm + OFF_RED);

    const int tid = threadIdx.x, wid = tid >> 5, l = tid & 31;
    const int b  = blockIdx.x;
    const int wm = wid >> 2;      // row half    -> rows wm*64..+63
    const int wn = wid & 3;       // col quarter -> cols wn*32..+31 = one atom

    if (tid < 65) red[tid] = 0.0f;

    // ---- prefetch atom chunk 0 into buf 0 ----
    {
        const uint4* g = (const uint4*)g_at_h;
        uint32_t d = sb + OFF_AT(0);
#pragma unroll
        for (int t = 0; t < 4; ++t) {
            int i = t * 256 + tid;
            cp16(d + i * 16, g + i);
        }
        CP_COMMIT();
    }

    // ---- x tile: scaled fp16 hi/lo into SW128 smem ----
    const float4* xg = (const float4*)(x + (size_t)b * NNOD * NDIM);
#pragma unroll
    for (int t = 0; t < 8; ++t) {
        int idx = t * 256 + tid;               // 0..2047 float4
        int row = idx >> 4, k4 = idx & 15;
        float4 v = xg[idx];
        float s0 = v.x * S1f, s1 = v.y * S1f, s2 = v.z * S1f, s3 = v.w * S1f;
        __half h0 = __float2half_rn(s0), h1 = __float2half_rn(s1);
        __half h2 = __float2half_rn(s2), h3 = __float2half_rn(s3);
        __half l0 = __float2half_rn(s0 - __half2float(h0));
        __half l1 = __float2half_rn(s1 - __half2float(h1));
        __half l2 = __float2half_rn(s2 - __half2float(h2));
        __half l3 = __float2half_rn(s3 - __half2float(h3));
        uint32_t off = sw128((uint32_t)(row * 128 + k4 * 8));
        uint2 ph, pl;
        ph.x = (uint32_t)__half_as_ushort(h0) | ((uint32_t)__half_as_ushort(h1) << 16);
        ph.y = (uint32_t)__half_as_ushort(h2) | ((uint32_t)__half_as_ushort(h3) << 16);
        pl.x = (uint32_t)__half_as_ushort(l0) | ((uint32_t)__half_as_ushort(l1) << 16);
        pl.y = (uint32_t)__half_as_ushort(l2) | ((uint32_t)__half_as_ushort(l3) << 16);
        *(uint2*)(sm + OFF_XHI + off) = ph;
        *(uint2*)(sm + OFF_XLO + off) = pl;
    }
    if (tid < NNOD) {
        const float4* xr4 = (const float4*)(x + ((size_t)b * NNOD + tid) * NDIM);
        float s = 0.0f;
#pragma unroll
        for (int k = 0; k < 16; ++k) {
            float4 v = xr4[k];
            s = fmaf(v.x, v.x, fmaf(v.y, v.y, fmaf(v.z, v.z, fmaf(v.w, v.w, s))));
        }
        xnL[tid] = s * A2f;
    }
    CP_WAIT0();
    __syncthreads();

    // ---- per-thread ldmatrix address components ----
    const uint32_t mask  = (uint32_t)((l & 7) << 4);
    const uint32_t aRow  = (uint32_t)((wm * 64 + (l & 7) + ((l >> 3) & 1) * 8) * 128);
    const uint32_t klowA = (uint32_t)(((l >> 4) & 1) * 16);
    const uint32_t bRow  = (uint32_t)((wn * 32 + (l & 7) + ((l >> 4) & 1) * 8) * 128);
    const uint32_t klowB = (uint32_t)(((l >> 3) & 1) * 16);

    // hoisted row norms: rows wm*64 + mt*16 + (l>>2) + r*8
    float xr[8];
#pragma unroll
    for (int mt = 0; mt < 4; ++mt) {
        xr[mt * 2 + 0] = xnL[wm * 64 + mt * 16 + (l >> 2)];
        xr[mt * 2 + 1] = xnL[wm * 64 + mt * 16 + (l >> 2) + 8];
    }

    // ---- 17 chunks: 16 atom chunks + k_xx (B = Xhi) ----
#pragma unroll 1
    for (int ch = 0; ch < 17; ++ch) {
        const int buf = ch & 1;

        if (ch + 1 < 16) {   // prefetch next atom chunk into buf^1
            const uint4* g = (const uint4*)g_at_h + (size_t)(ch + 1) * 1024;
            uint32_t d = sb + OFF_AT(buf ^ 1);
#pragma unroll
            for (int t = 0; t < 4; ++t) {
                int i = t * 256 + tid;
                cp16(d + i * 16, g + i);
            }
        }
        CP_COMMIT();

        const uint32_t Ahi = sb + OFF_XHI, Alo = sb + OFF_XLO;
        const uint32_t Bb  = (ch == 16) ? Ahi : (sb + OFF_AT(buf));

        float c[4][4][4];
#pragma unroll
        for (int mt = 0; mt < 4; ++mt)
#pragma unroll
            for (int nt = 0; nt < 4; ++nt)
#pragma unroll
                for (int q = 0; q < 4; ++q) c[mt][nt][q] = 0.0f;

#pragma unroll
        for (int ks = 0; ks < 4; ++ks) {
            const uint32_t colA = ((uint32_t)(ks * 32) + klowA) ^ mask;
            const uint32_t colB = ((uint32_t)(ks * 32) + klowB) ^ mask;
            uint32_t b0[4], b1[4];
            ldsm4(b0, Bb + bRow + colB);            // cols wn*32 .. +15
            ldsm4(b1, Bb + bRow + 2048 + colB);     // cols +16 .. +31
#pragma unroll
            for (int mt = 0; mt < 4; ++mt) {        // pass 1: A = x_hi
                uint32_t a[4];
                ldsm4(a, Ahi + aRow + mt * 2048 + colA);
                mma16816(c[mt][0], a, b0 + 0);
                mma16816(c[mt][1], a, b0 + 2);
                mma16816(c[mt][2], a, b1 + 0);
                mma16816(c[mt][3], a, b1 + 2);
            }
#pragma unroll
            for (int mt = 0; mt < 4; ++mt) {        // pass 2: A = x_lo
                uint32_t a[4];
                ldsm4(a, Alo + aRow + mt * 2048 + colA);
                mma16816(c[mt][0], a, b0 + 0);
                mma16816(c[mt][1], a, b0 + 2);
                mma16816(c[mt][2], a, b1 + 0);
                mma16816(c[mt][3], a, b1 + 2);
            }
        }

        // ---- epilogue: exp2 + per-atom reduction ----
        float cn[8];
        if (ch == 16) {
#pragma unroll
            for (int nt = 0; nt < 4; ++nt) {
                cn[nt * 2 + 0] = xnL[wn * 32 + nt * 8 + (l & 3) * 2];
                cn[nt * 2 + 1] = xnL[wn * 32 + nt * 8 + (l & 3) * 2 + 1];
            }
        } else {
#pragma unroll
            for (int nt = 0; nt < 4; ++nt) {
                cn[nt * 2 + 0] = __ldg(&g_anL[ch * 128 + wn * 32 + nt * 8 + (l & 3) * 2]);
                cn[nt * 2 + 1] = __ldg(&g_anL[ch * 128 + wn * 32 + nt * 8 + (l & 3) * 2 + 1]);
            }
        }
        float s0 = 0.f, s1 = 0.f;
#pragma unroll
        for (int mt = 0; mt < 4; ++mt)
#pragma unroll
            for (int nt = 0; nt < 4; ++nt) {
                s0 += fexp2(c[mt][nt][0] - xr[mt * 2 + 0] - cn[nt * 2 + 0]);
                s1 += fexp2(c[mt][nt][1] - xr[mt * 2 + 0] - cn[nt * 2 + 1]);
                s0 += fexp2(c[mt][nt][2] - xr[mt * 2 + 1] - cn[nt * 2 + 0]);
                s1 += fexp2(c[mt][nt][3] - xr[mt * 2 + 1] - cn[nt * 2 + 1]);
            }
        float s = wred(s0 + s1);
        if (l == 0) atomicAdd(&red[(ch == 16) ? 64 : (ch * 4 + wn)], s);

        CP_WAIT0();
        __syncthreads();
    }

    if (tid < NC) {
        float kxy = red[tid] * (1.0f / (NNOD * NK));
        float kxx = red[64]  * (1.0f / (NNOD * NNOD));
        out[b * NC + tid] = kxx + g_kyy[tid] - 2.0f * kxy;
    }
}

// ---------------------------------------------------------------------------
extern "C" void kernel_launch(void* const* d_in, const int* in_sizes, int n_in,
                              void* d_out, int out_size)
{
    const float* x     = (const float*)d_in[0];
    const float* atoms = (const float*)d_in[1];
    if (n_in >= 2 && in_sizes[0] == CKTOT * NDIM && in_sizes[1] == NBS * NNOD * NDIM) {
        x     = (const float*)d_in[1];
        atoms = (const float*)d_in[0];
    }
    float* out = (float*)d_out;

    cudaFuncSetAttribute(mmd_main, cudaFuncAttributeMaxDynamicSharedMemorySize, SMEM_DYN);

    mmd_prep<<<NC, 128>>>(atoms);
    mmd_main<<<NBS, 256, SMEM_DYN>>>(x, out);
}

// round 5
// speedup vs baseline: 6.0622x; 1.6371x over previous
#include <cuda_runtime.h>
#include <cuda_fp16.h>
#include <cstdint>

#define NBS   256
#define NNOD  128
#define NDIM  64
#define NC    64
#define NK    32
#define CKTOT (NC*NK)

#define A2f 0.0225421101f     // log2(e)/64
#define C2f 0.0450842203f     // 2*log2(e)/64
#define S1f 0.21233045f       // sqrt(C2f): scale inputs so MMA acc = C2*dot

// ---------------- smem layout (byte offsets from 1KB-aligned base) ----------
#define OFF_XHI   0           // 128x64 fp16 SW128 (16KB)
#define OFF_AT(b) (16384 + (b)*16384)    // atom chunk bufs (fp16, 16KB each)
#define OFF_XNL   49152       // float[128]
#define OFF_RED   49664       // float[65]
#define SMEM_DYN  (50176 + 1024)

// pre-converted atoms: scaled fp16, already in SW128 tile byte order
static __device__ uint16_t g_at_h[CKTOT * NDIM];
static __device__ float    g_anL[CKTOT];   // A2*||atom_ck||^2
static __device__ float    g_kyy[NC];

// ---------------------------------------------------------------------------
__device__ __forceinline__ uint32_t smem_u32(const void* p) {
    uint32_t a;
    asm("{ .reg .u64 t; cvta.to.shared.u64 t, %1; cvt.u32.u64 %0, t; }" : "=r"(a) : "l"(p));
    return a;
}
__device__ __forceinline__ uint32_t sw128(uint32_t o) { return o ^ ((o >> 3) & 0x70); }

__device__ __forceinline__ void ldsm4(uint32_t r[4], uint32_t addr) {
    asm volatile("ldmatrix.sync.aligned.m8n8.x4.shared.b16 {%0,%1,%2,%3}, [%4];"
                 : "=r"(r[0]), "=r"(r[1]), "=r"(r[2]), "=r"(r[3]) : "r"(addr));
}
__device__ __forceinline__ void mma16816(float c[4], const uint32_t a[4], const uint32_t b[2]) {
    asm volatile("mma.sync.aligned.m16n8k16.row.col.f32.f16.f16.f32 "
                 "{%0,%1,%2,%3}, {%4,%5,%6,%7}, {%8,%9}, {%0,%1,%2,%3};"
                 : "+f"(c[0]), "+f"(c[1]), "+f"(c[2]), "+f"(c[3])
                 : "r"(a[0]), "r"(a[1]), "r"(a[2]), "r"(a[3]), "r"(b[0]), "r"(b[1]));
}
__device__ __forceinline__ void cp16(uint32_t dst, const void* src) {
    asm volatile("cp.async.cg.shared.global [%0], [%1], 16;" :: "r"(dst), "l"(src) : "memory");
}
#define CP_COMMIT() asm volatile("cp.async.commit_group;" ::: "memory")
#define CP_WAIT0()  asm volatile("cp.async.wait_group 0;" ::: "memory")

// MUFU exp2 — runs on the SFU pipe, parallel to FMA/tensor
__device__ __forceinline__ float mexp2(float x) {
    float r;
    asm("ex2.approx.f32 %0, %1;" : "=f"(r) : "f"(x));
    return r;
}
// FMA-pipe exp2 for the (tiny) prep kernel
__device__ __forceinline__ float fexp2(float x) {
    float r = x + 12582912.0f;
    int   m = __float_as_int(r);
    float t = x - (r - 12582912.0f);
    float p =            1.3333558e-3f;
    p = fmaf(p, t, 9.6181291e-3f);
    p = fmaf(p, t, 5.5504109e-2f);
    p = fmaf(p, t, 2.4022651e-1f);
    p = fmaf(p, t, 6.9314718e-1f);
    p = fmaf(p, t, 1.0f);
    return __int_as_float(__float_as_int(p) + (m << 23));
}
__device__ __forceinline__ float wred(float v) {
#pragma unroll
    for (int o = 16; o; o >>= 1) v += __shfl_xor_sync(0xffffffffu, v, o);
    return v;
}

// ---------------------------------------------------------------------------
// Prep: per-ck-row scaled norms, k_yy, fp16 atoms in pre-swizzled layout
// ---------------------------------------------------------------------------
__global__ void mmd_prep(const float* __restrict__ atoms)
{
    __shared__ float at[NK][NDIM + 4];
    __shared__ float anl[NK];
    __shared__ float ssum;
    const int c = blockIdx.x, tid = threadIdx.x;

    const float4* ag = (const float4*)(atoms + (size_t)c * NK * NDIM);
#pragma unroll
    for (int t = 0; t < 4; ++t) {
        int idx = t * 128 + tid;
        int row = idx >> 4, k4 = idx & 15;
        *(float4*)&at[row][k4 * 4] = ag[idx];
    }
    if (tid == 0) ssum = 0.0f;
    __syncthreads();

    if (tid < NK) {
        float s = 0.0f;
#pragma unroll
        for (int k = 0; k < NDIM; k += 4) {
            float4 v = *(const float4*)&at[tid][k];
            s = fmaf(v.x, v.x, fmaf(v.y, v.y, fmaf(v.z, v.z, fmaf(v.w, v.w, s))));
        }
        anl[tid] = s;
        g_anL[c * NK + tid] = s * A2f;
    }
    __syncthreads();

#pragma unroll
    for (int t = 0; t < 16; ++t) {
        int idx = t * 128 + tid;            // 0..2047
        int r = idx >> 6, k = idx & 63;
        float v = at[r][k] * S1f;
        int gr = c * NK + r;
        int chunk = gr >> 7, rin = gr & 127;
        uint32_t off = sw128((uint32_t)(rin * 128 + k * 2));
        g_at_h[(uint32_t)chunk * 8192u + (off >> 1)] =
            __half_as_ushort(__float2half_rn(v));
    }

    float ps = 0.0f;
#pragma unroll
    for (int t = 0; t < 8; ++t) {
        int p = t * 128 + tid;
        int i = p >> 5, j = p & 31;
        float dot = 0.0f;
#pragma unroll
        for (int k = 0; k < NDIM; k += 4) {
            float4 a  = *(const float4*)&at[i][k];
            float4 bb = *(const float4*)&at[j][k];
            dot = fmaf(a.x, bb.x, fmaf(a.y, bb.y, fmaf(a.z, bb.z, fmaf(a.w, bb.w, dot))));
        }
        ps += fexp2(fmaf(dot, C2f, -A2f * (anl[i] + anl[j])));
    }
    ps = wred(ps);
    if ((tid & 31) == 0) atomicAdd(&ssum, ps);
    __syncthreads();
    if (tid == 0) g_kyy[c] = ssum * (1.0f / (NK * NK));
}

// ---------------------------------------------------------------------------
// Main: one CTA per graph; single-pass fp16 mma, norms folded into acc init,
// MUFU ex2 epilogue.
// ---------------------------------------------------------------------------
__global__ void __launch_bounds__(256, 2)
mmd_main(const float* __restrict__ x, float* __restrict__ out)
{
    extern __shared__ char sraw[];
    char* sm = (char*)(((uintptr_t)sraw + 1023) & ~(uintptr_t)1023);
    const uint32_t sb = smem_u32(sm);

    float* xnL = (float*)(sm + OFF_XNL);
    float* red = (float*)(sm + OFF_RED);

    const int tid = threadIdx.x, wid = tid >> 5, l = tid & 31;
    const int b  = blockIdx.x;
    const int wm = wid >> 2;      // row half    -> rows wm*64..+63
    const int wn = wid & 3;       // col quarter -> cols wn*32..+31 = one atom

    if (tid < 65) red[tid] = 0.0f;

    // ---- prefetch atom chunk 0 into buf 0 ----
    {
        const uint4* g = (const uint4*)g_at_h;
        uint32_t d = sb + OFF_AT(0);
#pragma unroll
        for (int t = 0; t < 4; ++t) {
            int i = t * 256 + tid;
            cp16(d + i * 16, g + i);
        }
        CP_COMMIT();
    }

    // ---- x tile: scaled fp16 into SW128 smem ----
    const float4* xg = (const float4*)(x + (size_t)b * NNOD * NDIM);
#pragma unroll
    for (int t = 0; t < 8; ++t) {
        int idx = t * 256 + tid;               // 0..2047 float4
        int row = idx >> 4, k4 = idx & 15;
        float4 v = xg[idx];
        __half h0 = __float2half_rn(v.x * S1f), h1 = __float2half_rn(v.y * S1f);
        __half h2 = __float2half_rn(v.z * S1f), h3 = __float2half_rn(v.w * S1f);
        uint32_t off = sw128((uint32_t)(row * 128 + k4 * 8));
        uint2 ph;
        ph.x = (uint32_t)__half_as_ushort(h0) | ((uint32_t)__half_as_ushort(h1) << 16);
        ph.y = (uint32_t)__half_as_ushort(h2) | ((uint32_t)__half_as_ushort(h3) << 16);
        *(uint2*)(sm + OFF_XHI + off) = ph;
    }
    if (tid < NNOD) {
        const float4* xr4 = (const float4*)(x + ((size_t)b * NNOD + tid) * NDIM);
        float s = 0.0f;
#pragma unroll
        for (int k = 0; k < 16; ++k) {
            float4 v = xr4[k];
            s = fmaf(v.x, v.x, fmaf(v.y, v.y, fmaf(v.z, v.z, fmaf(v.w, v.w, s))));
        }
        xnL[tid] = s * A2f;
    }
    CP_WAIT0();
    __syncthreads();

    // ---- per-thread ldmatrix address components ----
    const uint32_t mask  = (uint32_t)((l & 7) << 4);
    const uint32_t aRow  = (uint32_t)((wm * 64 + (l & 7) + ((l >> 3) & 1) * 8) * 128);
    const uint32_t klowA = (uint32_t)(((l >> 4) & 1) * 16);
    const uint32_t bRow  = (uint32_t)((wn * 32 + (l & 7) + ((l >> 4) & 1) * 8) * 128);
    const uint32_t klowB = (uint32_t)(((l >> 3) & 1) * 16);

    // negated row norms: rows wm*64 + mt*16 + (l>>2) + r*8
    float nxr[8];
#pragma unroll
    for (int mt = 0; mt < 4; ++mt) {
        nxr[mt * 2 + 0] = -xnL[wm * 64 + mt * 16 + (l >> 2)];
        nxr[mt * 2 + 1] = -xnL[wm * 64 + mt * 16 + (l >> 2) + 8];
    }

    // ---- 17 chunks: 16 atom chunks + k_xx (B = Xhi) ----
#pragma unroll 1
    for (int ch = 0; ch < 17; ++ch) {
        const int buf = ch & 1;

        if (ch + 1 < 16) {   // prefetch next atom chunk into buf^1
            const uint4* g = (const uint4*)g_at_h + (size_t)(ch + 1) * 1024;
            uint32_t d = sb + OFF_AT(buf ^ 1);
#pragma unroll
            for (int t = 0; t < 4; ++t) {
                int i = t * 256 + tid;
                cp16(d + i * 16, g + i);
            }
        }
        CP_COMMIT();

        const uint32_t Ahi = sb + OFF_XHI;
        const uint32_t Bb  = (ch == 16) ? Ahi : (sb + OFF_AT(buf));

        // column norms (loads overlap the MMA below)
        float cn[8];
        if (ch == 16) {
#pragma unroll
            for (int nt = 0; nt < 4; ++nt) {
                cn[nt * 2 + 0] = xnL[wn * 32 + nt * 8 + (l & 3) * 2];
                cn[nt * 2 + 1] = xnL[wn * 32 + nt * 8 + (l & 3) * 2 + 1];
            }
        } else {
#pragma unroll
            for (int nt = 0; nt < 4; ++nt) {
                cn[nt * 2 + 0] = __ldg(&g_anL[ch * 128 + wn * 32 + nt * 8 + (l & 3) * 2]);
                cn[nt * 2 + 1] = __ldg(&g_anL[ch * 128 + wn * 32 + nt * 8 + (l & 3) * 2 + 1]);
            }
        }

        // accumulators init to -(||x||^2 + ||a||^2) scaled -> epilogue = ex2(c)
        float c[4][4][4];
#pragma unroll
        for (int mt = 0; mt < 4; ++mt)
#pragma unroll
            for (int nt = 0; nt < 4; ++nt) {
                c[mt][nt][0] = nxr[mt * 2 + 0] - cn[nt * 2 + 0];
                c[mt][nt][1] = nxr[mt * 2 + 0] - cn[nt * 2 + 1];
                c[mt][nt][2] = nxr[mt * 2 + 1] - cn[nt * 2 + 0];
                c[mt][nt][3] = nxr[mt * 2 + 1] - cn[nt * 2 + 1];
            }

#pragma unroll
        for (int ks = 0; ks < 4; ++ks) {
            const uint32_t colA = ((uint32_t)(ks * 32) + klowA) ^ mask;
            const uint32_t colB = ((uint32_t)(ks * 32) + klowB) ^ mask;
            uint32_t b0[4], b1[4];
            ldsm4(b0, Bb + bRow + colB);            // cols wn*32 .. +15
            ldsm4(b1, Bb + bRow + 2048 + colB);     // cols +16 .. +31
#pragma unroll
            for (int mt = 0; mt < 4; ++mt) {
                uint32_t a[4];
                ldsm4(a, Ahi + aRow + mt * 2048 + colA);
                mma16816(c[mt][0], a, b0 + 0);
                mma16816(c[mt][1], a, b0 + 2);
                mma16816(c[mt][2], a, b1 + 0);
                mma16816(c[mt][3], a, b1 + 2);
            }
        }

        // ---- epilogue: MUFU ex2 + accumulate ----
        float s0 = 0.f, s1 = 0.f, s2 = 0.f, s3 = 0.f;
#pragma unroll
        for (int mt = 0; mt < 4; ++mt)
#pragma unroll
            for (int nt = 0; nt < 4; ++nt) {
                s0 += mexp2(c[mt][nt][0]);
                s1 += mexp2(c[mt][nt][1]);
                s2 += mexp2(c[mt][nt][2]);
                s3 += mexp2(c[mt][nt][3]);
            }
        float s = wred((s0 + s1) + (s2 + s3));
        if (l == 0) atomicAdd(&red[(ch == 16) ? 64 : (ch * 4 + wn)], s);

        CP_WAIT0();
        __syncthreads();
    }

    if (tid < NC) {
        float kxy = red[tid] * (1.0f / (NNOD * NK));
        float kxx = red[64]  * (1.0f / (NNOD * NNOD));
        out[b * NC + tid] = kxx + g_kyy[tid] - 2.0f * kxy;
    }
}

// ---------------------------------------------------------------------------
extern "C" void kernel_launch(void* const* d_in, const int* in_sizes, int n_in,
                              void* d_out, int out_size)
{
    const float* x     = (const float*)d_in[0];
    const float* atoms = (const float*)d_in[1];
    if (n_in >= 2 && in_sizes[0] == CKTOT * NDIM && in_sizes[1] == NBS * NNOD * NDIM) {
        x     = (const float*)d_in[1];
        atoms = (const float*)d_in[0];
    }
    float* out = (float*)d_out;

    cudaFuncSetAttribute(mmd_main, cudaFuncAttributeMaxDynamicSharedMemorySize, SMEM_DYN);

    mmd_prep<<<NC, 128>>>(atoms);
    mmd_main<<<NBS, 256, SMEM_DYN>>>(x, out);
}

// round 7
// speedup vs baseline: 6.1532x; 1.0150x over previous
#include <cuda_runtime.h>
#include <cuda_fp16.h>
#include <cstdint>

#define NBS   256
#define NNOD  128
#define NDIM  64
#define NC    64
#define NK    32
#define CKTOT (NC*NK)

#define A2f 0.0225421101f     // log2(e)/64
#define C2f 0.0450842203f     // 2*log2(e)/64
#define S1f 0.21233045f       // sqrt(C2f): scale inputs so MMA acc = C2*dot

// ---------------- smem layout (byte offsets from 1KB-aligned base) ----------
#define OFF_XHI   0                     // 128x64 fp16 SW128 (16KB)
#define OFF_AT(b) (16384 + (b)*16384)   // 4 atom chunk bufs (fp16, 16KB each)
#define OFF_XNL   81920                 // float[128]
#define OFF_RED   82432                 // float[65]
#define SMEM_DYN  (82944 + 1024)

// pre-converted atoms: scaled fp16, already in SW128 tile byte order
static __device__ uint16_t g_at_h[CKTOT * NDIM];
static __device__ float    g_anL[CKTOT];   // A2*||atom_ck||^2
static __device__ float    g_kyy[NC];

// ---------------------------------------------------------------------------
__device__ __forceinline__ uint32_t smem_u32(const void* p) {
    uint32_t a;
    asm("{ .reg .u64 t; cvta.to.shared.u64 t, %1; cvt.u32.u64 %0, t; }" : "=r"(a) : "l"(p));
    return a;
}
__device__ __forceinline__ uint32_t sw128(uint32_t o) { return o ^ ((o >> 3) & 0x70); }

__device__ __forceinline__ void ldsm4(uint32_t r[4], uint32_t addr) {
    asm volatile("ldmatrix.sync.aligned.m8n8.x4.shared.b16 {%0,%1,%2,%3}, [%4];"
                 : "=r"(r[0]), "=r"(r[1]), "=r"(r[2]), "=r"(r[3]) : "r"(addr));
}
__device__ __forceinline__ void mma16816(float c[4], const uint32_t a[4], const uint32_t b[2]) {
    asm volatile("mma.sync.aligned.m16n8k16.row.col.f32.f16.f16.f32 "
                 "{%0,%1,%2,%3}, {%4,%5,%6,%7}, {%8,%9}, {%0,%1,%2,%3};"
                 : "+f"(c[0]), "+f"(c[1]), "+f"(c[2]), "+f"(c[3])
                 : "r"(a[0]), "r"(a[1]), "r"(a[2]), "r"(a[3]), "r"(b[0]), "r"(b[1]));
}
__device__ __forceinline__ void cp16(uint32_t dst, const void* src) {
    asm volatile("cp.async.cg.shared.global [%0], [%1], 16;" :: "r"(dst), "l"(src) : "memory");
}
#define CP_COMMIT() asm volatile("cp.async.commit_group;" ::: "memory")
#define CP_WAIT1()  asm volatile("cp.async.wait_group 1;" ::: "memory")

// MUFU exp2 (fp32 — f16x2 variant failed the 1e-3 gate in R6)
__device__ __forceinline__ float mexp2(float x) {
    float r;
    asm("ex2.approx.f32 %0, %1;" : "=f"(r) : "f"(x));
    return r;
}
// FMA-pipe exp2 for the (tiny) prep kernel
__device__ __forceinline__ float fexp2(float x) {
    float r = x + 12582912.0f;
    int   m = __float_as_int(r);
    float t = x - (r - 12582912.0f);
    float p =            1.3333558e-3f;
    p = fmaf(p, t, 9.6181291e-3f);
    p = fmaf(p, t, 5.5504109e-2f);
    p = fmaf(p, t, 2.4022651e-1f);
    p = fmaf(p, t, 6.9314718e-1f);
    p = fmaf(p, t, 1.0f);
    return __int_as_float(__float_as_int(p) + (m << 23));
}
__device__ __forceinline__ float wred(float v) {
#pragma unroll
    for (int o = 16; o; o >>= 1) v += __shfl_xor_sync(0xffffffffu, v, o);
    return v;
}

// ---------------------------------------------------------------------------
// Prep: per-ck-row scaled norms, k_yy, fp16 atoms in pre-swizzled layout
// ---------------------------------------------------------------------------
__global__ void mmd_prep(const float* __restrict__ atoms)
{
    __shared__ float at[NK][NDIM + 4];
    __shared__ float anl[NK];
    __shared__ float ssum;
    const int c = blockIdx.x, tid = threadIdx.x;

    const float4* ag = (const float4*)(atoms + (size_t)c * NK * NDIM);
#pragma unroll
    for (int t = 0; t < 4; ++t) {
        int idx = t * 128 + tid;
        int row = idx >> 4, k4 = idx & 15;
        *(float4*)&at[row][k4 * 4] = ag[idx];
    }
    if (tid == 0) ssum = 0.0f;
    __syncthreads();

    if (tid < NK) {
        float s = 0.0f;
#pragma unroll
        for (int k = 0; k < NDIM; k += 4) {
            float4 v = *(const float4*)&at[tid][k];
            s = fmaf(v.x, v.x, fmaf(v.y, v.y, fmaf(v.z, v.z, fmaf(v.w, v.w, s))));
        }
        anl[tid] = s;
        g_anL[c * NK + tid] = s * A2f;
    }
    __syncthreads();

#pragma unroll
    for (int t = 0; t < 16; ++t) {
        int idx = t * 128 + tid;            // 0..2047
        int r = idx >> 6, k = idx & 63;
        float v = at[r][k] * S1f;
        int gr = c * NK + r;
        int chunk = gr >> 7, rin = gr & 127;
        uint32_t off = sw128((uint32_t)(rin * 128 + k * 2));
        g_at_h[(uint32_t)chunk * 8192u + (off >> 1)] =
            __half_as_ushort(__float2half_rn(v));
    }

    float ps = 0.0f;
#pragma unroll
    for (int t = 0; t < 8; ++t) {
        int p = t * 128 + tid;
        int i = p >> 5, j = p & 31;
        float dot = 0.0f;
#pragma unroll
        for (int k = 0; k < NDIM; k += 4) {
            float4 a  = *(const float4*)&at[i][k];
            float4 bb = *(const float4*)&at[j][k];
            dot = fmaf(a.x, bb.x, fmaf(a.y, bb.y, fmaf(a.z, bb.z, fmaf(a.w, bb.w, dot))));
        }
        ps += fexp2(fmaf(dot, C2f, -A2f * (anl[i] + anl[j])));
    }
    ps = wred(ps);
    if ((tid & 31) == 0) atomicAdd(&ssum, ps);
    __syncthreads();
    if (tid == 0) g_kyy[c] = ssum * (1.0f / (NK * NK));
}

// ---------------------------------------------------------------------------
// One 128x128 chunk: MMA (norms folded into acc init) + fp32 ex2 epilogue.
// ---------------------------------------------------------------------------
__device__ __forceinline__ float chunk_sum(
    uint32_t Ahi, uint32_t Bb,
    uint32_t aRow, uint32_t bRow, uint32_t klowA, uint32_t klowB, uint32_t mask,
    const float nxr[8], const float cn[8])
{
    float c[4][4][4];
#pragma unroll
    for (int mt = 0; mt < 4; ++mt)
#pragma unroll
        for (int nt = 0; nt < 4; ++nt) {
            c[mt][nt][0] = nxr[mt * 2 + 0] - cn[nt * 2 + 0];
            c[mt][nt][1] = nxr[mt * 2 + 0] - cn[nt * 2 + 1];
            c[mt][nt][2] = nxr[mt * 2 + 1] - cn[nt * 2 + 0];
            c[mt][nt][3] = nxr[mt * 2 + 1] - cn[nt * 2 + 1];
        }

#pragma unroll
    for (int ks = 0; ks < 4; ++ks) {
        const uint32_t colA = ((uint32_t)(ks * 32) + klowA) ^ mask;
        const uint32_t colB = ((uint32_t)(ks * 32) + klowB) ^ mask;
        uint32_t b0[4], b1[4];
        ldsm4(b0, Bb + bRow + colB);            // cols wn*32 .. +15
        ldsm4(b1, Bb + bRow + 2048 + colB);     // cols +16 .. +31
#pragma unroll
        for (int mt = 0; mt < 4; ++mt) {
            uint32_t a[4];
            ldsm4(a, Ahi + aRow + mt * 2048 + colA);
            mma16816(c[mt][0], a, b0 + 0);
            mma16816(c[mt][1], a, b0 + 2);
            mma16816(c[mt][2], a, b1 + 0);
            mma16816(c[mt][3], a, b1 + 2);
        }
    }

    // epilogue: fp32 MUFU ex2 + 4 independent FADD chains
    float s0 = 0.f, s1 = 0.f, s2 = 0.f, s3 = 0.f;
#pragma unroll
    for (int mt = 0; mt < 4; ++mt)
#pragma unroll
        for (int nt = 0; nt < 4; ++nt) {
            s0 += mexp2(c[mt][nt][0]);
            s1 += mexp2(c[mt][nt][1]);
            s2 += mexp2(c[mt][nt][2]);
            s3 += mexp2(c[mt][nt][3]);
        }
    return (s0 + s1) + (s2 + s3);
}

// ---------------------------------------------------------------------------
// Main: one CTA per graph; kxx first (overlaps prefetch), then 8 chunk-pairs.
// ---------------------------------------------------------------------------
__global__ void __launch_bounds__(256, 2)
mmd_main(const float* __restrict__ x, float* __restrict__ out)
{
    extern __shared__ char sraw[];
    char* sm = (char*)(((uintptr_t)sraw + 1023) & ~(uintptr_t)1023);
    const uint32_t sb = smem_u32(sm);

    float* xnL = (float*)(sm + OFF_XNL);
    float* red = (float*)(sm + OFF_RED);

    const int tid = threadIdx.x, wid = tid >> 5, l = tid & 31;
    const int b  = blockIdx.x;
    const int wm = wid >> 2;      // row half    -> rows wm*64..+63
    const int wn = wid & 3;       // col quarter -> cols wn*32..+31 = one atom

    if (tid < 65) red[tid] = 0.0f;

    // ---- prefetch chunks 0,1 into bufs 0,1 (one group) ----
    {
        const uint4* g = (const uint4*)g_at_h;
        uint32_t d = sb + OFF_AT(0);
#pragma unroll
        for (int t = 0; t < 8; ++t) {
            int i = t * 256 + tid;               // 0..2047 -> 32KB (2 chunks)
            cp16(d + i * 16, g + i);
        }
        CP_COMMIT();
    }

    // ---- x tile: scaled fp16 into SW128 smem ----
    const float4* xg = (const float4*)(x + (size_t)b * NNOD * NDIM);
#pragma unroll
    for (int t = 0; t < 8; ++t) {
        int idx = t * 256 + tid;               // 0..2047 float4
        int row = idx >> 4, k4 = idx & 15;
        float4 v = xg[idx];
        __half h0 = __float2half_rn(v.x * S1f), h1 = __float2half_rn(v.y * S1f);
        __half h2 = __float2half_rn(v.z * S1f), h3 = __float2half_rn(v.w * S1f);
        uint32_t off = sw128((uint32_t)(row * 128 + k4 * 8));
        uint2 ph;
        ph.x = (uint32_t)__half_as_ushort(h0) | ((uint32_t)__half_as_ushort(h1) << 16);
        ph.y = (uint32_t)__half_as_ushort(h2) | ((uint32_t)__half_as_ushort(h3) << 16);
        *(uint2*)(sm + OFF_XHI + off) = ph;
    }
    if (tid < NNOD) {
        const float4* xr4 = (const float4*)(x + ((size_t)b * NNOD + tid) * NDIM);
        float s = 0.0f;
#pragma unroll
        for (int k = 0; k < 16; ++k) {
            float4 v = xr4[k];
            s = fmaf(v.x, v.x, fmaf(v.y, v.y, fmaf(v.z, v.z, fmaf(v.w, v.w, s))));
        }
        xnL[tid] = s * A2f;
    }
    __syncthreads();

    // ---- per-thread ldmatrix address components ----
    const uint32_t mask  = (uint32_t)((l & 7) << 4);
    const uint32_t aRow  = (uint32_t)((wm * 64 + (l & 7) + ((l >> 3) & 1) * 8) * 128);
    const uint32_t klowA = (uint32_t)(((l >> 4) & 1) * 16);
    const uint32_t bRow  = (uint32_t)((wn * 32 + (l & 7) + ((l >> 4) & 1) * 8) * 128);
    const uint32_t klowB = (uint32_t)(((l >> 3) & 1) * 16);
    const uint32_t Ahi   = sb + OFF_XHI;

    // negated row norms: rows wm*64 + mt*16 + (l>>2) + r*8
    float nxr[8];
#pragma unroll
    for (int mt = 0; mt < 4; ++mt) {
        nxr[mt * 2 + 0] = -xnL[wm * 64 + mt * 16 + (l >> 2)];
        nxr[mt * 2 + 1] = -xnL[wm * 64 + mt * 16 + (l >> 2) + 8];
    }

    // ---- k_xx chunk first (B = x tile; overlaps the chunk-0/1 prefetch) ----
    {
        float cn[8];
#pragma unroll
        for (int nt = 0; nt < 4; ++nt) {
            cn[nt * 2 + 0] = xnL[wn * 32 + nt * 8 + (l & 3) * 2];
            cn[nt * 2 + 1] = xnL[wn * 32 + nt * 8 + (l & 3) * 2 + 1];
        }
        float s = wred(chunk_sum(Ahi, Ahi, aRow, bRow, klowA, klowB, mask, nxr, cn));
        if (l == 0) atomicAdd(&red[64], s);
    }

    // ---- 8 pairs of atom chunks ----
#pragma unroll 1
    for (int p = 0; p < 8; ++p) {
        __syncthreads();                         // prior pair's reads complete
        if (p < 7) {                             // prefetch chunks 2p+2, 2p+3
            const uint4* g = (const uint4*)g_at_h + (size_t)(2 * p + 2) * 1024;
            uint32_t d0 = sb + OFF_AT((2 * p + 2) & 3);
            uint32_t d1 = sb + OFF_AT((2 * p + 3) & 3);
#pragma unroll
            for (int t = 0; t < 4; ++t) {
                int i = t * 256 + tid;
                cp16(d0 + i * 16, g + i);
                cp16(d1 + i * 16, g + 1024 + i);
            }
        }
        CP_COMMIT();
        CP_WAIT1();                              // chunks 2p, 2p+1 landed
        __syncthreads();

#pragma unroll
        for (int h = 0; h < 2; ++h) {
            const int ch = 2 * p + h;
            float cn[8];
#pragma unroll
            for (int nt = 0; nt < 4; ++nt) {
                cn[nt * 2 + 0] = __ldg(&g_anL[ch * 128 + wn * 32 + nt * 8 + (l & 3) * 2]);
                cn[nt * 2 + 1] = __ldg(&g_anL[ch * 128 + wn * 32 + nt * 8 + (l & 3) * 2 + 1]);
            }
            float s = wred(chunk_sum(Ahi, sb + OFF_AT(ch & 3),
                                     aRow, bRow, klowA, klowB, mask, nxr, cn));
            if (l == 0) atomicAdd(&red[ch * 4 + wn], s);
        }
    }

    __syncthreads();
    if (tid < NC) {
        float kxy = red[tid] * (1.0f / (NNOD * NK));
        float kxx = red[64]  * (1.0f / (NNOD * NNOD));
        out[b * NC + tid] = kxx + g_kyy[tid] - 2.0f * kxy;
    }
}

// ---------------------------------------------------------------------------
extern "C" void kernel_launch(void* const* d_in, const int* in_sizes, int n_in,
                              void* d_out, int out_size)
{
    const float* x     = (const float*)d_in[0];
    const float* atoms = (const float*)d_in[1];
    if (n_in >= 2 && in_sizes[0] == CKTOT * NDIM && in_sizes[1] == NBS * NNOD * NDIM) {
        x     = (const float*)d_in[1];
        atoms = (const float*)d_in[0];
    }
    float* out = (float*)d_out;

    cudaFuncSetAttribute(mmd_main, cudaFuncAttributeMaxDynamicSharedMemorySize, SMEM_DYN);

    mmd_prep<<<NC, 128>>>(atoms);
    mmd_main<<<NBS, 256, SMEM_DYN>>>(x, out);
}